// round 10
// baseline (speedup 1.0000x reference)
#include <cuda_runtime.h>
#include <cstdint>

// ---------------- Problem constants ----------------
#define E_TOTAL   500000
#define TILE_M    256
#define NTILES    ((E_TOTAL + TILE_M - 1) / TILE_M)   // 1954
#define NTHREADS  256

// ---------------- SMEM layout (bytes) ----------------
// W: 5 chunks, each [64 n x 64 k] tf32 = 16KB -> 80KB (loaded once)
// A: 2 chunk buffers [256 rows x 64 k] tf32 = 64KB each
#define SM_W       0
#define SM_B0      (5 * 16384)             // 81920
#define SM_B1      (SM_B0 + 65536)         // 147456
#define SMEM_TOTAL (SM_B1 + 65536)         // 212992 = 208KB (1 CTA/SM)

// ---------------- helpers ----------------
__device__ __forceinline__ uint32_t smem_u32(const void* p) {
    uint32_t a;
    asm("{ .reg .u64 t; cvta.to.shared.u64 t, %1; cvt.u32.u64 %0, t; }"
        : "=r"(a) : "l"(p));
    return a;
}

__device__ __forceinline__ uint32_t f2tf32(float f) {
    uint32_t r;
    asm("cvt.rna.tf32.f32 %0, %1;" : "=r"(r) : "f"(f));
    return r;
}

// Tile layout: [rows x 64 cols] tf32, 256B/row, cols k-permuted per 16-col
// group: quad (grp,t) holds cols {16grp+t, +4, +8, +12}.
// Swizzle: XOR byte bits[6:4] with sw(row)=((row&1)<<2)|(row&2)|((row>>2)&1).
__device__ __forceinline__ uint32_t tileoff(int row, int grp, int t) {
    uint32_t o  = (uint32_t)(row * 256 + grp * 64 + t * 16);
    uint32_t sw = (((uint32_t)row & 1u) << 2) | ((uint32_t)row & 2u) |
                  (((uint32_t)row >> 2) & 1u);
    return o ^ (sw << 4);
}

__device__ __forceinline__ void sts128(uint32_t addr, uint32_t a, uint32_t b,
                                       uint32_t c, uint32_t d) {
    asm volatile("st.shared.v4.b32 [%0], {%1,%2,%3,%4};"
                 :: "r"(addr), "r"(a), "r"(b), "r"(c), "r"(d) : "memory");
}

__device__ __forceinline__ void lds128(uint32_t addr, uint32_t* r) {
    asm volatile("ld.shared.v4.b32 {%0,%1,%2,%3}, [%4];"
                 : "=r"(r[0]), "=r"(r[1]), "=r"(r[2]), "=r"(r[3])
                 : "r"(addr));
}

__device__ __forceinline__ void mma_tf32(float* c, uint32_t a0, uint32_t a1,
                                         uint32_t a2, uint32_t a3,
                                         uint32_t b0, uint32_t b1) {
    asm volatile(
        "mma.sync.aligned.m16n8k8.row.col.f32.tf32.tf32.f32 "
        "{%0,%1,%2,%3},{%4,%5,%6,%7},{%8,%9},{%0,%1,%2,%3};"
        : "+f"(c[0]), "+f"(c[1]), "+f"(c[2]), "+f"(c[3])
        : "r"(a0), "r"(a1), "r"(a2), "r"(a3), "r"(b0), "r"(b1));
}

// 4x4 transpose across 4 consecutive lanes (sub = lane&3), in-place.
__device__ __forceinline__ void transpose4(float4& v, int sub) {
    float t0 = (sub & 1) ? v.x : v.y;
    float t1 = (sub & 1) ? v.z : v.w;
    t0 = __shfl_xor_sync(0xffffffffu, t0, 1);
    t1 = __shfl_xor_sync(0xffffffffu, t1, 1);
    if (sub & 1) { v.x = t0; v.z = t1; } else { v.y = t0; v.w = t1; }
    float t2 = (sub & 2) ? v.x : v.z;
    float t3 = (sub & 2) ? v.y : v.w;
    t2 = __shfl_xor_sync(0xffffffffu, t2, 2);
    t3 = __shfl_xor_sync(0xffffffffu, t3, 2);
    if (sub & 2) { v.x = t2; v.y = t3; } else { v.z = t2; v.w = t3; }
}

// In-thread repack for W staging (thread holds all 4 quads of one group).
__device__ __forceinline__ void sts_group_w(uint32_t base, int row, int grp,
                                            const float4* v) {
    const float* f = (const float*)v;
#pragma unroll
    for (int t = 0; t < 4; t++) {
        sts128(base + tileoff(row, grp, t),
               f2tf32(f[0 * 4 + t]), f2tf32(f[1 * 4 + t]),
               f2tf32(f[2 * 4 + t]), f2tf32(f[3 * 4 + t]));
    }
}

// ---- cooperative gather/store: warp owns 32 edges, processed in 2 halves ----
// Lane: q = lid&15 (quad within 256B row), half = lid>>4 (edge parity).
// Half hf covers edges [base+16hf, base+16hf+16): 8 passes of 2 edges.
__device__ __forceinline__ void gather_x8(const float* __restrict__ x, int base,
                                          int hf, int q, int half, float4* D) {
#pragma unroll
    for (int k = 0; k < 8; k++) {
        int e = base + 16 * hf + 2 * k + half;
        if (e > E_TOTAL - 1) e = E_TOTAL - 1;
        D[k] = __ldg((const float4*)x + (size_t)e * 16 + q);
    }
}

// comp: lane l holds neighbor index for edge we0+l (all 32 lanes).
__device__ __forceinline__ void gather_nbr8(const float* __restrict__ x, int comp,
                                            int hf, int q, int half, float4* D) {
#pragma unroll
    for (int k = 0; k < 8; k++) {
        int idx = __shfl_sync(0xffffffffu, comp, 16 * hf + 2 * k + half);
        float4 v = make_float4(0.f, 0.f, 0.f, 0.f);
        if (idx >= 0) v = __ldg((const float4*)x + (size_t)idx * 16 + q);
        D[k] = v;
    }
}

__device__ __forceinline__ void minmax8(float4* a, float4* b) {
#pragma unroll
    for (int i = 0; i < 8; i++) {
        float4 u = a[i], v = b[i];
        a[i] = make_float4(fminf(u.x, v.x), fminf(u.y, v.y),
                           fminf(u.z, v.z), fminf(u.w, v.w));
        b[i] = make_float4(fmaxf(u.x, v.x), fmaxf(u.y, v.y),
                           fmaxf(u.z, v.z), fmaxf(u.w, v.w));
    }
}

// Transpose (cross-lane) + convert + STS one half-stream (8 edge-pairs).
__device__ __forceinline__ void xpose_sts8(uint32_t buf, int we0, int hf,
                                           int half, int grp, int sub,
                                           const float4* S) {
#pragma unroll
    for (int k = 0; k < 8; k++) {
        float4 v = S[k];
        transpose4(v, sub);
        int row = we0 + 16 * hf + 2 * k + half;
        sts128(buf + tileoff(row, grp, sub),
               f2tf32(v.x), f2tf32(v.y), f2tf32(v.z), f2tf32(v.w));
    }
}

// One K=64 chunk of MMA for this warp's m64 x n32 block.
__device__ __forceinline__ void mma_chunk(uint32_t aB, uint32_t wB, int wm,
                                          int wn, int g, int tig,
                                          float acc[4][4][4]) {
#pragma unroll
    for (int t = 0; t < 4; t++) {
        uint32_t Bf[4][4];
#pragma unroll
        for (int nf = 0; nf < 4; nf++)
            lds128(wB + tileoff(wn * 32 + nf * 8 + g, t, tig), Bf[nf]);
        uint32_t Af[4][2][4];
#pragma unroll
        for (int ms = 0; ms < 4; ms++)
#pragma unroll
            for (int rh = 0; rh < 2; rh++)
                lds128(aB + tileoff(wm * 64 + ms * 16 + rh * 8 + g, t, tig),
                       Af[ms][rh]);
#pragma unroll
        for (int ms = 0; ms < 4; ms++)
#pragma unroll
            for (int nf = 0; nf < 4; nf++)
#pragma unroll
                for (int s = 0; s < 2; s++)
                    mma_tf32(acc[ms][nf],
                             Af[ms][0][2 * s], Af[ms][1][2 * s],
                             Af[ms][0][2 * s + 1], Af[ms][1][2 * s + 1],
                             Bf[nf][2 * s], Bf[nf][2 * s + 1]);
    }
}

// ---------------- kernel ----------------
// K=320 chunks: c0:x c1:min01 c2:max01 c3:min23 c4:max23
// TILE_M=256, 8 warps, 1 CTA/SM (208KB smem). Uniform warps:
// producer: warp owns 32 edges (2 halves of 16); consumer: m64 x n32 (4m x 2n).
// Bias folded into accumulator init; epilogue is pure store.
__global__ void __launch_bounds__(NTHREADS)
meshconv_kernel(const float* __restrict__ x, const int* __restrict__ nbr,
                const float* __restrict__ W, const float* __restrict__ bias,
                float* __restrict__ out) {
    extern __shared__ char smem[];
    const uint32_t sb = smem_u32(smem);
    const int tid = threadIdx.x;
    const int lid = tid & 31, wid = tid >> 5;
    // consumer identity
    const int wm = wid & 3, wn = wid >> 2;
    const int g = lid >> 2, tig = lid & 3;
    // producer identity
    const int q = lid & 15, half = lid >> 4, sub = lid & 3, grp = q >> 2;
    const int we0 = wid * 32;

    const uint32_t b0 = sb + SM_B0, b1 = sb + SM_B1;

    // ---- stage W once ----
#pragma unroll
    for (int c = 0; c < 5; c++) {
        int n = tid & 63;
        int gw = tid >> 6;
        float4 v[4];
#pragma unroll
        for (int i = 0; i < 4; i++)
            v[i] = ((const float4*)W)[(size_t)n * 80 + c * 16 + gw * 4 + i];
        sts_group_w(sb + SM_W + (uint32_t)c * 16384u, n, gw, v);
    }

    // bias fragment (init value for accumulators)
    float bv[4][2];
#pragma unroll
    for (int nf = 0; nf < 4; nf++) {
        int bc = wn * 32 + nf * 8 + tig * 2;
        bv[nf][0] = __ldg(bias + bc);
        bv[nf][1] = __ldg(bias + bc + 1);
    }

    // ---- prologue: NB + x-half0 for first tile ----
    int tile = blockIdx.x;
    int base = tile * TILE_M + we0;
    int NBx, NBy, NBz, NBw;
    {
        int e = base + lid;
        if (e > E_TOTAL - 1) e = E_TOTAL - 1;
        int4 nb4 = __ldg((const int4*)nbr + e);
        NBx = nb4.x; NBy = nb4.y; NBz = nb4.z; NBw = nb4.w;
    }
    float4 XQ0[8];
    gather_x8(x, base, 0, q, half, XQ0);

    __syncthreads();   // W staged

    for (; tile < NTILES; tile += gridDim.x) {
        int tn = tile + gridDim.x;
        if (tn >= NTILES) tn = tile;
        const int nbase = tn * TILE_M + we0;
        const int tbase = tile * TILE_M;

        float acc[4][4][4];
#pragma unroll
        for (int ms = 0; ms < 4; ms++)
#pragma unroll
            for (int nf = 0; nf < 4; nf++) {
                acc[ms][nf][0] = bv[nf][0];
                acc[ms][nf][1] = bv[nf][1];
                acc[ms][nf][2] = bv[nf][0];
                acc[ms][nf][3] = bv[nf][1];
            }

        // s-1: STS c0 (x) both halves; pre-issue pair0 half0 gathers
        xpose_sts8(b0, we0, 0, half, grp, sub, XQ0);
        {
            float4 XQ1[8];
            gather_x8(x, base, 1, q, half, XQ1);
            xpose_sts8(b0, we0, 1, half, grp, sub, XQ1);
        }
        float4 Pa[8], Pb[8];                     // pair gather staging (h0)
        gather_nbr8(x, NBx, 0, q, half, Pa);
        gather_nbr8(x, NBy, 0, q, half, Pb);
        __syncthreads();

        // s0: minmax p0h0, STS min->b1, keep max; same for h1; mma c0(b0)
        float4 MX0[8], MX1[8];                   // held max01 streams
        minmax8(Pa, Pb);
        xpose_sts8(b1, we0, 0, half, grp, sub, Pa);
#pragma unroll
        for (int i = 0; i < 8; i++) MX0[i] = Pb[i];
        gather_nbr8(x, NBx, 1, q, half, Pa);
        gather_nbr8(x, NBy, 1, q, half, Pb);
        minmax8(Pa, Pb);
        xpose_sts8(b1, we0, 1, half, grp, sub, Pa);
#pragma unroll
        for (int i = 0; i < 8; i++) MX1[i] = Pb[i];
        mma_chunk(b0, sb + SM_W + 0 * 16384u, wm, wn, g, tig, acc);
        __syncthreads();

        // s1: STS c2(max01)->b0 both halves; pre-issue pair1 h0; mma c1(b1)
        xpose_sts8(b0, we0, 0, half, grp, sub, MX0);
        xpose_sts8(b0, we0, 1, half, grp, sub, MX1);
        gather_nbr8(x, NBz, 0, q, half, Pa);
        gather_nbr8(x, NBw, 0, q, half, Pb);
        mma_chunk(b1, sb + SM_W + 1 * 16384u, wm, wn, g, tig, acc);
        __syncthreads();

        // s2: minmax p1h0, STS min->b1, keep max; h1 same; mma c2(b0)
        minmax8(Pa, Pb);
        xpose_sts8(b1, we0, 0, half, grp, sub, Pa);
#pragma unroll
        for (int i = 0; i < 8; i++) MX0[i] = Pb[i];
        gather_nbr8(x, NBz, 1, q, half, Pa);
        gather_nbr8(x, NBw, 1, q, half, Pb);
        minmax8(Pa, Pb);
        xpose_sts8(b1, we0, 1, half, grp, sub, Pa);
#pragma unroll
        for (int i = 0; i < 8; i++) MX1[i] = Pb[i];
        mma_chunk(b0, sb + SM_W + 2 * 16384u, wm, wn, g, tig, acc);
        __syncthreads();

        // s3: STS c4(max23)->b0 both halves; mma c3(b1)
        xpose_sts8(b0, we0, 0, half, grp, sub, MX0);
        xpose_sts8(b0, we0, 1, half, grp, sub, MX1);
        mma_chunk(b1, sb + SM_W + 3 * 16384u, wm, wn, g, tig, acc);
        __syncthreads();

        // s4: mma c4(b0); prefetch next NB + x-half0; epilogue (pure store)
        mma_chunk(b0, sb + SM_W + 4 * 16384u, wm, wn, g, tig, acc);
        {
            int e = nbase + lid;
            if (e > E_TOTAL - 1) e = E_TOTAL - 1;
            int4 nb4 = __ldg((const int4*)nbr + e);
            NBx = nb4.x; NBy = nb4.y; NBz = nb4.z; NBw = nb4.w;
        }
        gather_x8(x, nbase, 0, q, half, XQ0);
        base = nbase;

#pragma unroll
        for (int ms = 0; ms < 4; ms++) {
#pragma unroll
            for (int nf = 0; nf < 4; nf++) {
                const int e0  = tbase + wm * 64 + ms * 16 + g;
                const int e1  = e0 + 8;
                const int col = wn * 32 + nf * 8 + tig * 2;
                if (e0 < E_TOTAL)
                    *(float2*)(out + (size_t)e0 * 64 + col) =
                        make_float2(acc[ms][nf][0], acc[ms][nf][1]);
                if (e1 < E_TOTAL)
                    *(float2*)(out + (size_t)e1 * 64 + col) =
                        make_float2(acc[ms][nf][2], acc[ms][nf][3]);
            }
        }
        __syncthreads();   // protect b0 before next tile's STS c0
    }
}

// ---------------- launch ----------------
extern "C" void kernel_launch(void* const* d_in, const int* in_sizes, int n_in,
                              void* d_out, int out_size) {
    const float* x   = (const float*)d_in[0];
    const int*   nbr = (const int*)d_in[1];
    const float* W   = (const float*)d_in[2];
    const float* b   = (const float*)d_in[3];
    float* out = (float*)d_out;

    int nsm = 0;
    cudaDeviceGetAttribute(&nsm, cudaDevAttrMultiProcessorCount, 0);
    if (nsm <= 0) nsm = 148;

    cudaFuncSetAttribute(meshconv_kernel,
                         cudaFuncAttributeMaxDynamicSharedMemorySize, SMEM_TOTAL);
    meshconv_kernel<<<nsm, NTHREADS, SMEM_TOTAL>>>(x, nbr, W, b, out);
}

// round 11
// speedup vs baseline: 1.1620x; 1.1620x over previous
#include <cuda_runtime.h>
#include <cstdint>

// ---------------- Problem constants ----------------
#define E_TOTAL   500000
#define TILE_M    128
#define NTILES    ((E_TOTAL + TILE_M - 1) / TILE_M)   // 3907
#define NTHREADS  256

// SMEM: 3 A-chunk buffers [128 rows x 64 k] tf32 = 32KB each -> 96KB, 2 CTAs/SM
#define SMEM_TOTAL (3 * 32768)

// Repacked W in fragment order: idx = c*1024 + wn*512 + (nf*4+t)*32 + lane.
// Quad holds tf32-converted W[n, c*64+16t+tig + {0,4,8,12}], n = wn*32+nf*8+g.
__device__ uint4 Wrep[5120];   // 80KB

// ---------------- helpers ----------------
__device__ __forceinline__ uint32_t smem_u32(const void* p) {
    uint32_t a;
    asm("{ .reg .u64 t; cvta.to.shared.u64 t, %1; cvt.u32.u64 %0, t; }"
        : "=r"(a) : "l"(p));
    return a;
}

__device__ __forceinline__ uint32_t f2tf32(float f) {
    uint32_t r;
    asm("cvt.rna.tf32.f32 %0, %1;" : "=r"(r) : "f"(f));
    return r;
}

// A-tile layout: [rows x 64 cols] tf32, 256B/row, cols k-permuted per 16-col
// group: quad (grp,t) holds cols {16grp+t, +4, +8, +12}.
// Swizzle: XOR byte bits[6:4] with sw(row)=((row&1)<<2)|(row&2)|((row>>2)&1).
__device__ __forceinline__ uint32_t tileoff(int row, int grp, int t) {
    uint32_t o  = (uint32_t)(row * 256 + grp * 64 + t * 16);
    uint32_t sw = (((uint32_t)row & 1u) << 2) | ((uint32_t)row & 2u) |
                  (((uint32_t)row >> 2) & 1u);
    return o ^ (sw << 4);
}

__device__ __forceinline__ void sts128(uint32_t addr, uint32_t a, uint32_t b,
                                       uint32_t c, uint32_t d) {
    asm volatile("st.shared.v4.b32 [%0], {%1,%2,%3,%4};"
                 :: "r"(addr), "r"(a), "r"(b), "r"(c), "r"(d) : "memory");
}

__device__ __forceinline__ void lds128(uint32_t addr, uint32_t* r) {
    asm volatile("ld.shared.v4.b32 {%0,%1,%2,%3}, [%4];"
                 : "=r"(r[0]), "=r"(r[1]), "=r"(r[2]), "=r"(r[3])
                 : "r"(addr));
}

__device__ __forceinline__ void mma_tf32(float* c, uint32_t a0, uint32_t a1,
                                         uint32_t a2, uint32_t a3,
                                         uint32_t b0, uint32_t b1) {
    asm volatile(
        "mma.sync.aligned.m16n8k8.row.col.f32.tf32.tf32.f32 "
        "{%0,%1,%2,%3},{%4,%5,%6,%7},{%8,%9},{%0,%1,%2,%3};"
        : "+f"(c[0]), "+f"(c[1]), "+f"(c[2]), "+f"(c[3])
        : "r"(a0), "r"(a1), "r"(a2), "r"(a3), "r"(b0), "r"(b1));
}

// 4x4 transpose across 4 consecutive lanes (sub = lane&3), in-place.
__device__ __forceinline__ void transpose4(float4& v, int sub) {
    float t0 = (sub & 1) ? v.x : v.y;
    float t1 = (sub & 1) ? v.z : v.w;
    t0 = __shfl_xor_sync(0xffffffffu, t0, 1);
    t1 = __shfl_xor_sync(0xffffffffu, t1, 1);
    if (sub & 1) { v.x = t0; v.z = t1; } else { v.y = t0; v.w = t1; }
    float t2 = (sub & 2) ? v.x : v.z;
    float t3 = (sub & 2) ? v.y : v.w;
    t2 = __shfl_xor_sync(0xffffffffu, t2, 2);
    t3 = __shfl_xor_sync(0xffffffffu, t3, 2);
    if (sub & 2) { v.x = t2; v.y = t3; } else { v.z = t2; v.w = t3; }
}

// ---------------- W repack kernel (runs once per launch, tiny) ----------------
__global__ void repack_w_kernel(const float* __restrict__ W) {
    int idx = blockIdx.x * blockDim.x + threadIdx.x;
    if (idx >= 5120) return;
    int tig = idx & 3;
    int g   = (idx >> 2) & 7;
    int t   = (idx >> 5) & 3;
    int nf  = (idx >> 7) & 3;
    int wn  = (idx >> 9) & 1;
    int c   = idx >> 10;
    int n   = wn * 32 + nf * 8 + g;
    int col = c * 64 + t * 16 + tig;
    const float* wr = W + (size_t)n * 320 + col;
    uint4 v;
    v.x = f2tf32(wr[0]);
    v.y = f2tf32(wr[4]);
    v.z = f2tf32(wr[8]);
    v.w = f2tf32(wr[12]);
    Wrep[idx] = v;
}

// ---------------- producer pieces ----------------
// Transpose + convert + STS one half-group (4 passes of 2 edges).
__device__ __forceinline__ void xpose_sts4h(uint32_t buf, int we0, int hg,
                                            int half, int grp, int sub,
                                            const float4* S) {
#pragma unroll
    for (int k = 0; k < 4; k++) {
        float4 v = S[k];
        transpose4(v, sub);
        int row = we0 + 8 * hg + 2 * k + half;
        sts128(buf + tileoff(row, grp, sub),
               f2tf32(v.x), f2tf32(v.y), f2tf32(v.z), f2tf32(v.w));
    }
}

// Gather one pair half-group, compute min/max, STS min into bufMin,
// return raw max stream in M (transposed at its own STS time).
__device__ __forceinline__ void pair_half(const float* __restrict__ x, int cA,
                                          int cB, int hg, int q, int half,
                                          int grp, int sub, int we0,
                                          uint32_t bufMin, float4* M) {
    float4 Pmin[4];
#pragma unroll
    for (int k = 0; k < 4; k++) {
        int l  = 8 * hg + 2 * k + half;
        int ia = __shfl_sync(0xffffffffu, cA, l);
        int ib = __shfl_sync(0xffffffffu, cB, l);
        float4 va = make_float4(0.f, 0.f, 0.f, 0.f);
        float4 vb = make_float4(0.f, 0.f, 0.f, 0.f);
        if (ia >= 0) va = __ldg((const float4*)x + (size_t)ia * 16 + q);
        if (ib >= 0) vb = __ldg((const float4*)x + (size_t)ib * 16 + q);
        Pmin[k] = make_float4(fminf(va.x, vb.x), fminf(va.y, vb.y),
                              fminf(va.z, vb.z), fminf(va.w, vb.w));
        M[k]    = make_float4(fmaxf(va.x, vb.x), fmaxf(va.y, vb.y),
                              fmaxf(va.z, vb.z), fmaxf(va.w, vb.w));
    }
    xpose_sts4h(bufMin, we0, hg, half, grp, sub, Pmin);
}

// Gather own-row x (coalesced) + STS, both half-groups, small transient regs.
__device__ __forceinline__ void stage_x(const float* __restrict__ x, int basew,
                                        uint32_t buf, int we0, int q, int half,
                                        int grp, int sub) {
#pragma unroll
    for (int hg = 0; hg < 2; hg++) {
        float4 Xh[4];
#pragma unroll
        for (int k = 0; k < 4; k++) {
            int e = basew + 8 * hg + 2 * k + half;
            if (e > E_TOTAL - 1) e = E_TOTAL - 1;
            Xh[k] = __ldg((const float4*)x + (size_t)e * 16 + q);
        }
        xpose_sts4h(buf, we0, hg, half, grp, sub, Xh);
    }
}

// ---------------- consumer: one K=64 chunk, warp tile m32 x n32 ----------------
// wrc = Wrep + c*1024 + wn*512 + lid  (B fragments via coalesced LDG, L1-hot).
__device__ __forceinline__ void mma_chunk(uint32_t aB, const uint4* wrc, int wm,
                                          int g, int tig, float acc[2][4][4]) {
#pragma unroll
    for (int t = 0; t < 4; t++) {
        uint4 Bq[4];
#pragma unroll
        for (int nf = 0; nf < 4; nf++)
            Bq[nf] = __ldg(wrc + (nf * 4 + t) * 32);
        uint32_t Af[2][2][4];
#pragma unroll
        for (int ms = 0; ms < 2; ms++)
#pragma unroll
            for (int rh = 0; rh < 2; rh++)
                lds128(aB + tileoff(wm * 32 + ms * 16 + rh * 8 + g, t, tig),
                       Af[ms][rh]);
#pragma unroll
        for (int ms = 0; ms < 2; ms++)
#pragma unroll
            for (int nf = 0; nf < 4; nf++) {
                mma_tf32(acc[ms][nf],
                         Af[ms][0][0], Af[ms][1][0], Af[ms][0][1], Af[ms][1][1],
                         Bq[nf].x, Bq[nf].y);
                mma_tf32(acc[ms][nf],
                         Af[ms][0][2], Af[ms][1][2], Af[ms][0][3], Af[ms][1][3],
                         Bq[nf].z, Bq[nf].w);
            }
    }
}

// ---------------- main kernel ----------------
// K=320 chunks: c0:x c1:min01 c2:max01 c3:min23 c4:max23
// TILE_M=128, 256 thr, 2 CTAs/SM (96KB smem, <=128 regs). Uniform warps:
// producer warp owns 16 edges (2 half-groups of 8); consumer m32 x n32 (4m x 2n).
// 3-buffer ring: chunk j of local tile tcnt lives in buf (2*tcnt + j) % 3.
// Phases s0..s4, sync after s0..s3 only (s4 write-sets are disjoint from next s0).
__global__ void __launch_bounds__(NTHREADS, 2)
meshconv_kernel(const float* __restrict__ x, const int* __restrict__ nbr,
                const float* __restrict__ bias, float* __restrict__ out) {
    extern __shared__ char smem[];
    const uint32_t sb = smem_u32(smem);
    const int tid = threadIdx.x;
    const int lid = tid & 31, wid = tid >> 5;
    // consumer identity
    const int wm = wid & 3, wn = wid >> 2;
    const int g = lid >> 2, tig = lid & 3;
    // producer identity
    const int q = lid & 15, half = lid >> 4, sub = lid & 3, grp = q >> 2;
    const int we0 = wid * 16;

    // bias fragment (accumulator init values)
    float bv[4][2];
#pragma unroll
    for (int nf = 0; nf < 4; nf++) {
        int bc = wn * 32 + nf * 8 + tig * 2;
        bv[nf][0] = __ldg(bias + bc);
        bv[nf][1] = __ldg(bias + bc + 1);
    }

    const uint4* wrbase = Wrep + wn * 512 + lid;

    // ---- prologue: NB + stage c0 of first tile into buf 0 ----
    int tile = blockIdx.x;
    int base = tile * TILE_M + we0;
    int NBx, NBy, NBz, NBw;
    {
        int e = base + (lid & 15);
        if (e > E_TOTAL - 1) e = E_TOTAL - 1;
        int4 v = __ldg((const int4*)nbr + e);
        NBx = v.x; NBy = v.y; NBz = v.z; NBw = v.w;
    }
    stage_x(x, base, sb, we0, q, half, grp, sub);
    __syncthreads();

    int bc3 = 0;   // buffer rotation: buf(j) = (bc3 + j) % 3
    for (; tile < NTILES; tile += gridDim.x) {
        int tn = tile + gridDim.x;
        if (tn >= NTILES) tn = tile;
        const int nbase = tn * TILE_M + we0;
        const int tbase = tile * TILE_M;

        const int u1 = (bc3 + 1 == 3) ? 0 : bc3 + 1;
        const int u2 = (u1 + 1 == 3) ? 0 : u1 + 1;
        const uint32_t b_c0 = sb + (uint32_t)bc3 * 32768u;   // c0, c3
        const uint32_t b_c1 = sb + (uint32_t)u1 * 32768u;    // c1, c4
        const uint32_t b_c2 = sb + (uint32_t)u2 * 32768u;    // c2, next c0

        float acc[2][4][4];
#pragma unroll
        for (int ms = 0; ms < 2; ms++)
#pragma unroll
            for (int nf = 0; nf < 4; nf++) {
                acc[ms][nf][0] = bv[nf][0];
                acc[ms][nf][1] = bv[nf][1];
                acc[ms][nf][2] = bv[nf][0];
                acc[ms][nf][3] = bv[nf][1];
            }

        float4 MX0[4], MX1[4];   // held max streams (one pair at a time)

        // s0: pair0 -> min01 into b_c1 (hold max01); mma c0(b_c0)
        pair_half(x, NBx, NBy, 0, q, half, grp, sub, we0, b_c1, MX0);
        pair_half(x, NBx, NBy, 1, q, half, grp, sub, we0, b_c1, MX1);
        mma_chunk(b_c0, wrbase + 0 * 1024, wm, g, tig, acc);
        __syncthreads();

        // s1: STS max01 -> b_c2; pair1 -> min23 into b_c0 (hold max23); mma c1(b_c1)
        xpose_sts4h(b_c2, we0, 0, half, grp, sub, MX0);
        xpose_sts4h(b_c2, we0, 1, half, grp, sub, MX1);
        pair_half(x, NBz, NBw, 0, q, half, grp, sub, we0, b_c0, MX0);
        pair_half(x, NBz, NBw, 1, q, half, grp, sub, we0, b_c0, MX1);
        mma_chunk(b_c1, wrbase + 1 * 1024, wm, g, tig, acc);
        __syncthreads();

        // s2: STS max23 -> b_c1; prefetch next NB; mma c2(b_c2)
        xpose_sts4h(b_c1, we0, 0, half, grp, sub, MX0);
        xpose_sts4h(b_c1, we0, 1, half, grp, sub, MX1);
        int NBnx, NBny, NBnz, NBnw;
        {
            int e = nbase + (lid & 15);
            if (e > E_TOTAL - 1) e = E_TOTAL - 1;
            int4 v = __ldg((const int4*)nbr + e);
            NBnx = v.x; NBny = v.y; NBnz = v.z; NBnw = v.w;
        }
        mma_chunk(b_c2, wrbase + 2 * 1024, wm, g, tig, acc);
        __syncthreads();

        // s3: stage next tile's c0 (x) -> b_c2; mma c3(b_c0)
        stage_x(x, nbase, b_c2, we0, q, half, grp, sub);
        mma_chunk(b_c0, wrbase + 3 * 1024, wm, g, tig, acc);
        __syncthreads();

        // s4: mma c4(b_c1); rotate state; epilogue (pure STG, no smem -> no sync)
        mma_chunk(b_c1, wrbase + 4 * 1024, wm, g, tig, acc);
        NBx = NBnx; NBy = NBny; NBz = NBnz; NBw = NBnw;
        base = nbase;
        bc3 = u2;

#pragma unroll
        for (int ms = 0; ms < 2; ms++) {
#pragma unroll
            for (int nf = 0; nf < 4; nf++) {
                const int e0  = tbase + wm * 32 + ms * 16 + g;
                const int e1  = e0 + 8;
                const int col = wn * 32 + nf * 8 + tig * 2;
                if (e0 < E_TOTAL)
                    *(float2*)(out + (size_t)e0 * 64 + col) =
                        make_float2(acc[ms][nf][0], acc[ms][nf][1]);
                if (e1 < E_TOTAL)
                    *(float2*)(out + (size_t)e1 * 64 + col) =
                        make_float2(acc[ms][nf][2], acc[ms][nf][3]);
            }
        }
    }
}

// ---------------- launch ----------------
extern "C" void kernel_launch(void* const* d_in, const int* in_sizes, int n_in,
                              void* d_out, int out_size) {
    const float* x   = (const float*)d_in[0];
    const int*   nbr = (const int*)d_in[1];
    const float* W   = (const float*)d_in[2];
    const float* b   = (const float*)d_in[3];
    float* out = (float*)d_out;

    int nsm = 0;
    cudaDeviceGetAttribute(&nsm, cudaDevAttrMultiProcessorCount, 0);
    if (nsm <= 0) nsm = 148;

    repack_w_kernel<<<20, 256>>>(W);

    cudaFuncSetAttribute(meshconv_kernel,
                         cudaFuncAttributeMaxDynamicSharedMemorySize, SMEM_TOTAL);
    meshconv_kernel<<<2 * nsm, NTHREADS, SMEM_TOTAL>>>(x, nbr, b, out);
}